// round 13
// baseline (speedup 1.0000x reference)
#include <cuda_runtime.h>
#include <cuda_fp16.h>
#include <cstdint>

// ---------------------------------------------------------------------------
// Problem constants
// ---------------------------------------------------------------------------
#define EPSF 1e-8f

constexpr int NQ = 8192;     // queries
constexpr int NK = 524288;   // keys
constexpr int D  = 128;      // head_dim
constexpr int NF = 64;       // num_freqs
constexpr int NB = 128;      // num_bins
constexpr int DT = 192;      // D + NF  (GEMM K-dimension)

constexpr int STRIDE = 200;                    // fp16 elems per row (400B -> conflict-free ldmatrix)
constexpr int WBUF_BYTES = 128 * STRIDE * 2;   // 51,200 B

// ---------------------------------------------------------------------------
// Device scratch (no allocations allowed)
// ---------------------------------------------------------------------------
__device__ __align__(16) __half  g_Wh[128 * STRIDE];  // W fp16, [bin][k], stride 200
__device__ __align__(16) __half2 g_rph[NF * NB];      // rotated probe pairs fp16, [f][b]
__device__ __align__(16) __half2 g_ewmw[NF * NB];     // (eff_w, q_mag_w) fp16, [f][b]

// ---------------------------------------------------------------------------
// Helpers
// ---------------------------------------------------------------------------
__device__ __forceinline__ float sqrt_approx(float x) {
    float y;
    asm("sqrt.approx.f32 %0, %1;" : "=f"(y) : "f"(x));
    return y;
}

__device__ __forceinline__ uint32_t packh2(float a, float b) {
    __half2 t = __floats2half2_rn(a, b);
    return *reinterpret_cast<uint32_t*>(&t);
}

__device__ __forceinline__ uint32_t smem_u32(const void* p) {
    uint32_t a;
    asm("{ .reg .u64 t; cvta.to.shared.u64 t, %1; cvt.u32.u64 %0, t; }" : "=r"(a) : "l"(p));
    return a;
}

__device__ __forceinline__ void ldm4(uint32_t* r, uint32_t addr) {
    asm volatile("ldmatrix.sync.aligned.m8n8.x4.shared.b16 {%0,%1,%2,%3}, [%4];"
        : "=r"(r[0]), "=r"(r[1]), "=r"(r[2]), "=r"(r[3]) : "r"(addr));
}

__device__ __forceinline__ void mma16816(float* c, const uint32_t* a, const uint32_t* b) {
    asm volatile("mma.sync.aligned.m16n8k16.row.col.f32.f16.f16.f32 "
        "{%0,%1,%2,%3}, {%4,%5,%6,%7}, {%8,%9}, {%0,%1,%2,%3};"
        : "+f"(c[0]), "+f"(c[1]), "+f"(c[2]), "+f"(c[3])
        : "r"(a[0]), "r"(a[1]), "r"(a[2]), "r"(a[3]), "r"(b[0]), "r"(b[1]));
}

// ---------------------------------------------------------------------------
// Prep kernel: one block per bin, 64 threads (one per freq)
// ---------------------------------------------------------------------------
__global__ void prep_kernel(const float* __restrict__ angles,
                            const float* __restrict__ probes,
                            const float* __restrict__ kmw,
                            const float* __restrict__ qraw,
                            const float* __restrict__ qmw)
{
    __shared__ float red[2];
    const int b = blockIdx.x;
    const int f = threadIdx.x;   // 0..63

    float p0 = probes[b * D + 2 * f];
    float p1 = probes[b * D + 2 * f + 1];
    float s = fmaf(p0, p0, p1 * p1);
    #pragma unroll
    for (int o = 16; o; o >>= 1) s += __shfl_xor_sync(0xffffffffu, s, o);
    if ((f & 31) == 0) red[f >> 5] = s;
    __syncthreads();
    float inv = 1.0f / (sqrtf(red[0] + red[1]) + EPSF);
    p0 *= inv; p1 *= inv;

    float a  = angles[f];
    float ca = cosf(a), sa = sinf(a);
    float r0 = p0 * ca - p1 * sa;
    float r1 = p0 * sa + p1 * ca;

    g_Wh[b * STRIDE + 2 * f]     = __float2half_rn(r0);
    g_Wh[b * STRIDE + 2 * f + 1] = __float2half_rn(r1);
    g_Wh[b * STRIDE + D + f]     = __float2half_rn(kmw[b * NF + f]);
    if (f < 8) g_Wh[b * STRIDE + 192 + f] = __float2half_rn(0.f);

    g_rph[f * NB + b] = __floats2half2_rn(r0, r1);
    float x  = qraw[b * NF + f];
    float sp = fmaxf(x, 0.0f) + log1pf(expf(-fabsf(x)));
    g_ewmw[f * NB + b] = __floats2half2_rn(-sp, qmw[b * NF + f]);
}

// ---------------------------------------------------------------------------
// Fused kernel: blocks [0, KBLOCKS) do the K-path GEMM; the rest do Q-path.
// K path: 1024 threads, 32 warps as 8(M)x4(N) grid of 32x32 warp tiles,
// block tile 256x128, single A buffer, phase-separated convert/MMA.
// 32 warps/SM = 8 per SMSP -> hide ldmatrix->HMMA dependency latency.
// ---------------------------------------------------------------------------
constexpr int TILE_M   = 256;
constexpr int KTHREADS = 1024;
constexpr int TILES    = 2;
constexpr int KBLOCKS  = NK / (TILE_M * TILES);           // 1024
constexpr int FPT      = (TILE_M * (D / 4)) / KTHREADS;   // float4 per thread = 8

constexpr int QPB      = 64;
constexpr int QBLOCKS  = NQ / QPB;                        // 128

// kpath smem layout
constexpr int ABUF_BYTES = TILE_M * STRIDE * 2;  // 102,400
constexpr int OFF_WH    = 0;
constexpr int OFF_A     = OFF_WH + WBUF_BYTES;   //  51,200
constexpr int OFF_BIAS  = OFF_A + ABUF_BYTES;    // 153,600
constexpr int SMEM_SZ   = OFF_BIAS + 512;        // 154,112

// ---- K path body -----------------------------------------------------------
__device__ __forceinline__ void kpath_body(char* smc, const float* __restrict__ Kmat,
                                           const float* __restrict__ kbias,
                                           float* __restrict__ out)
{
    const uint32_t base = smem_u32(smc);
    float* sBias = reinterpret_cast<float*>(smc + OFF_BIAS);

    const int tid  = threadIdx.x;
    const int lane = tid & 31;
    const int wid  = tid >> 5;           // 0..31
    const int wm   = (wid & 7) * 32;     // warp M offset (8 groups of 32)
    const int wn   = (wid >> 3) * 32;    // warp N offset (4 groups of 32)

    // W -> smem (layout already final)
    {
        const int4* gw = reinterpret_cast<const int4*>(g_Wh);
        int4* sw = reinterpret_cast<int4*>(smc + OFF_WH);
        for (int i = tid; i < WBUF_BYTES / 16; i += KTHREADS) sw[i] = gw[i];
    }
    if (tid < NB) sBias[tid] = kbias[tid];

    // ldmatrix lane base addresses
    const int aRow = wm + (lane & 7) + ((lane >> 3) & 1) * 8;
    const int aK   = ((lane >> 4) & 1) * 8;
    const uint32_t aA = base + OFF_A + (uint32_t)(aRow * STRIDE + aK) * 2;
    const int bRow = wn + (lane & 7) + ((lane >> 4) & 1) * 8;
    const int bK   = ((lane >> 3) & 1) * 8;
    const uint32_t bA = base + OFF_WH + (uint32_t)(bRow * STRIDE + bK) * 2;

    constexpr uint32_t MSTEP = 16 * STRIDE * 2;   // 16 rows in bytes

    const size_t blockRow0 = (size_t)blockIdx.x * TILES * TILE_M;
    const float4* K4base = reinterpret_cast<const float4*>(Kmat);

    __syncthreads();   // W + bias visible

    for (int t = 0; t < TILES; t++) {
        const size_t rowBase = blockRow0 + (size_t)t * TILE_M;

        // ---- Phase 1: convert K rows f32 -> fp16 A (+ magnitudes), LDG direct
        {
            const float4* g = K4base + rowBase * (D / 4);
            #pragma unroll
            for (int ib = 0; ib < FPT / 2; ib++) {
                float4 vv[2];
                #pragma unroll
                for (int u = 0; u < 2; u++)
                    vv[u] = g[(ib * 2 + u) * KTHREADS + tid];
                #pragma unroll
                for (int u = 0; u < 2; u++) {
                    const int i = (ib * 2 + u) * KTHREADS + tid;
                    const int row = i >> 5, c4 = i & 31;
                    float4 v = vv[u];
                    const int e0 = row * STRIDE + 4 * c4;
                    *reinterpret_cast<uint2*>(smc + OFF_A + 2 * e0) =
                        make_uint2(packh2(v.x, v.y), packh2(v.z, v.w));
                    float m0 = sqrt_approx(fmaf(v.x, v.x, fmaf(v.y, v.y, EPSF)));
                    float m1 = sqrt_approx(fmaf(v.z, v.z, fmaf(v.w, v.w, EPSF)));
                    const int em = row * STRIDE + D + 2 * c4;
                    *reinterpret_cast<uint32_t*>(smc + OFF_A + 2 * em) = packh2(m0, m1);
                }
            }
        }
        __syncthreads();   // A ready

        // ---- Phase 2: MMA mainloop, 12 k-chunks, 2m x 4n8 positions
        float c[2][4][4];
        #pragma unroll
        for (int i = 0; i < 2; i++)
            #pragma unroll
            for (int j = 0; j < 4; j++)
                #pragma unroll
                for (int r = 0; r < 4; r++) c[i][j][r] = 0.0f;

        #pragma unroll
        for (int kc = 0; kc < DT / 16; kc++) {
            const uint32_t kB = (uint32_t)kc * 32;
            uint32_t af[2][4], bf[2][4];
            #pragma unroll
            for (int i = 0; i < 2; i++) ldm4(af[i], aA + i * MSTEP + kB);
            #pragma unroll
            for (int jj = 0; jj < 2; jj++) ldm4(bf[jj], bA + jj * MSTEP + kB);
            #pragma unroll
            for (int i = 0; i < 2; i++)
                #pragma unroll
                for (int j = 0; j < 4; j++)
                    mma16816(c[i][j], af[i], &bf[j >> 1][(j & 1) * 2]);
        }

        // ---- Epilogue: bias + STG.64 from accumulators
        float2* out2 = reinterpret_cast<float2*>(out);
        const size_t r0 = rowBase + wm + (lane >> 2);
        #pragma unroll
        for (int j = 0; j < 4; j++) {
            const int col = wn + j * 8 + (lane & 3) * 2;
            const float bx = sBias[col], by = sBias[col + 1];
            const int ch = col >> 1;
            #pragma unroll
            for (int i = 0; i < 2; i++) {
                const size_t row = r0 + i * 16;
                float2 v0 = make_float2(c[i][j][0] + bx, c[i][j][1] + by);
                float2 v1 = make_float2(c[i][j][2] + bx, c[i][j][3] + by);
                out2[row * (NB / 2) + ch] = v0;
                out2[(row + 8) * (NB / 2) + ch] = v1;
            }
        }
        __syncthreads();   // all LDSM reads of A done before next convert
    }
}

// ---- Q path body (64 queries per block, 1024 threads) ----------------------
// smem: [0,32768) sRPh | [32768,65536) sEWMW | [65536,98304) sQn f32[64*128]
//       [98304,106496) sQmag half[64*64] | [106496,106752) sInv | [106752,107264) sQB
__device__ __forceinline__ void qpath_body(char* smc, const float* __restrict__ Q,
                                           const float* __restrict__ qbias,
                                           float* __restrict__ outq, int qb)
{
    __half2* sRPh  = reinterpret_cast<__half2*>(smc);            // [f][b]
    __half2* sEWMW = reinterpret_cast<__half2*>(smc + 32768);    // [f][b]
    float*   sQn   = reinterpret_cast<float*>(smc + 65536);      // QPB*D
    __half*  sQmag = reinterpret_cast<__half*>(smc + 98304);     // QPB*NF
    float*   sInv  = reinterpret_cast<float*>(smc + 106496);     // QPB
    float*   sQB   = reinterpret_cast<float*>(smc + 106752);     // NB

    const int tid = threadIdx.x;
    {
        const int4* gr = reinterpret_cast<const int4*>(g_rph);
        const int4* ge = reinterpret_cast<const int4*>(g_ewmw);
        int4* sr = reinterpret_cast<int4*>(sRPh);
        int4* se = reinterpret_cast<int4*>(sEWMW);
        #pragma unroll
        for (int it = 0; it < 2; it++) {
            sr[it * KTHREADS + tid] = gr[it * KTHREADS + tid];
            se[it * KTHREADS + tid] = ge[it * KTHREADS + tid];
        }
    }
    if (tid < NB) sQB[tid] = qbias[tid];

    const int qbase = qb * QPB;
    for (int i = tid; i < QPB * D; i += KTHREADS)
        sQn[i] = Q[(size_t)qbase * D + i];
    __syncthreads();

    {   // L2 norms: 16 threads per query (1024 = 64*16)
        int q = tid >> 4, l16 = tid & 15;
        float s = 0.0f;
        #pragma unroll
        for (int j = 0; j < D / 16; j++) {
            float v = sQn[q * D + l16 + 16 * j];
            s = fmaf(v, v, s);
        }
        s += __shfl_down_sync(0xffffffffu, s, 8, 16);
        s += __shfl_down_sync(0xffffffffu, s, 4, 16);
        s += __shfl_down_sync(0xffffffffu, s, 2, 16);
        s += __shfl_down_sync(0xffffffffu, s, 1, 16);
        if (l16 == 0) sInv[q] = 1.0f / (sqrtf(s) + EPSF);
    }
    __syncthreads();
    for (int i = tid; i < QPB * D; i += KTHREADS)
        sQn[i] *= sInv[i >> 7];
    __syncthreads();
    for (int i = tid; i < QPB * NF; i += KTHREADS) {
        int q = i >> 6, f = i & 63;
        float a = sQn[q * D + 2 * f];
        float c = sQn[q * D + 2 * f + 1];
        sQmag[i] = __float2half_rn(sqrt_approx(fmaf(a, a, fmaf(c, c, EPSF))));
    }
    __syncthreads();

    const int b  = tid & 127;
    const int qg = tid >> 7;    // 0..7: 8 queries each
    float acc[8];
    #pragma unroll
    for (int j = 0; j < 8; j++) acc[j] = 0.0f;

    for (int f = 0; f < NF; f++) {
        float2 rp = __half22float2(sRPh[f * NB + b]);
        float2 em = __half22float2(sEWMW[f * NB + b]);   // x=eff_w, y=q_mag_w
        #pragma unroll
        for (int j = 0; j < 8; j++) {
            int q = qg * 8 + j;
            float2 qp = *reinterpret_cast<const float2*>(sQn + q * D + 2 * f);
            float d0 = rp.x - qp.x;
            float d1 = rp.y - qp.y;
            float dist = sqrt_approx(fmaf(d0, d0, fmaf(d1, d1, EPSF)));
            acc[j] = fmaf(dist, em.x, acc[j]);
            acc[j] = fmaf(__half2float(sQmag[q * NF + f]), em.y, acc[j]);
        }
    }

    #pragma unroll
    for (int j = 0; j < 8; j++) {
        int q = qbase + qg * 8 + j;
        outq[(size_t)q * NB + b] = acc[j] + sQB[b];
    }
}

// ---- Fused kernel -----------------------------------------------------------
__global__ void __launch_bounds__(KTHREADS, 1)
fused_kernel(const float* __restrict__ Kmat,
             const float* __restrict__ kbias,
             const float* __restrict__ Q,
             const float* __restrict__ qbias,
             float* __restrict__ out)
{
    extern __shared__ char smc[];
    if (blockIdx.x < KBLOCKS) {
        kpath_body(smc, Kmat, kbias, out);
    } else {
        qpath_body(smc, Q, qbias, out + (size_t)NK * NB, blockIdx.x - KBLOCKS);
    }
}

// ---------------------------------------------------------------------------
// Launch
// ---------------------------------------------------------------------------
extern "C" void kernel_launch(void* const* d_in, const int* in_sizes, int n_in,
                              void* d_out, int out_size)
{
    const float* Q      = (const float*)d_in[0];
    const float* Kmat   = (const float*)d_in[1];
    const float* angles = (const float*)d_in[2];
    const float* probes = (const float*)d_in[3];
    const float* kmw    = (const float*)d_in[4];
    const float* kbias  = (const float*)d_in[5];
    const float* qraw   = (const float*)d_in[6];
    const float* qmw    = (const float*)d_in[7];
    const float* qbias  = (const float*)d_in[8];
    float* out = (float*)d_out;

    cudaFuncSetAttribute(fused_kernel, cudaFuncAttributeMaxDynamicSharedMemorySize, SMEM_SZ);

    prep_kernel<<<NB, NF>>>(angles, probes, kmw, qraw, qmw);
    fused_kernel<<<KBLOCKS + QBLOCKS, KTHREADS, SMEM_SZ>>>(Kmat, kbias, Q, qbias, out);
}

// round 14
// speedup vs baseline: 1.1956x; 1.1956x over previous
#include <cuda_runtime.h>
#include <cuda_fp16.h>
#include <cstdint>

// ---------------------------------------------------------------------------
// Problem constants
// ---------------------------------------------------------------------------
#define EPSF 1e-8f

constexpr int NQ = 8192;     // queries
constexpr int NK = 524288;   // keys
constexpr int D  = 128;      // head_dim
constexpr int NF = 64;       // num_freqs
constexpr int NB = 128;      // num_bins
constexpr int DT = 192;      // D + NF  (GEMM K-dimension)

constexpr int STRIDE = 200;                    // fp16 elems per row (400B -> conflict-free ldmatrix)
constexpr int WBUF_BYTES = 128 * STRIDE * 2;   // 51,200 B

// ---------------------------------------------------------------------------
// Device scratch (no allocations allowed)
// ---------------------------------------------------------------------------
__device__ __align__(16) __half  g_Wh[128 * STRIDE];  // W fp16, [bin][k], stride 200
__device__ __align__(16) __half2 g_rph[NF * NB];      // rotated probe pairs fp16, [f][b]
__device__ __align__(16) __half2 g_ewmw[NF * NB];     // (eff_w, q_mag_w) fp16, [f][b]

// ---------------------------------------------------------------------------
// Helpers
// ---------------------------------------------------------------------------
__device__ __forceinline__ float sqrt_approx(float x) {
    float y;
    asm("sqrt.approx.f32 %0, %1;" : "=f"(y) : "f"(x));
    return y;
}

__device__ __forceinline__ uint32_t packh2(float a, float b) {
    __half2 t = __floats2half2_rn(a, b);
    return *reinterpret_cast<uint32_t*>(&t);
}

__device__ __forceinline__ uint32_t smem_u32(const void* p) {
    uint32_t a;
    asm("{ .reg .u64 t; cvta.to.shared.u64 t, %1; cvt.u32.u64 %0, t; }" : "=r"(a) : "l"(p));
    return a;
}

__device__ __forceinline__ void ldm4(uint32_t* r, uint32_t addr) {
    asm volatile("ldmatrix.sync.aligned.m8n8.x4.shared.b16 {%0,%1,%2,%3}, [%4];"
        : "=r"(r[0]), "=r"(r[1]), "=r"(r[2]), "=r"(r[3]) : "r"(addr));
}

__device__ __forceinline__ void mma16816(float* c, const uint32_t* a, const uint32_t* b) {
    asm volatile("mma.sync.aligned.m16n8k16.row.col.f32.f16.f16.f32 "
        "{%0,%1,%2,%3}, {%4,%5,%6,%7}, {%8,%9}, {%0,%1,%2,%3};"
        : "+f"(c[0]), "+f"(c[1]), "+f"(c[2]), "+f"(c[3])
        : "r"(a[0]), "r"(a[1]), "r"(a[2]), "r"(a[3]), "r"(b[0]), "r"(b[1]));
}

// ---------------------------------------------------------------------------
// Prep kernel: one block per bin, 64 threads (one per freq)
// ---------------------------------------------------------------------------
__global__ void prep_kernel(const float* __restrict__ angles,
                            const float* __restrict__ probes,
                            const float* __restrict__ kmw,
                            const float* __restrict__ qraw,
                            const float* __restrict__ qmw)
{
    __shared__ float red[2];
    const int b = blockIdx.x;
    const int f = threadIdx.x;   // 0..63

    float p0 = probes[b * D + 2 * f];
    float p1 = probes[b * D + 2 * f + 1];
    float s = fmaf(p0, p0, p1 * p1);
    #pragma unroll
    for (int o = 16; o; o >>= 1) s += __shfl_xor_sync(0xffffffffu, s, o);
    if ((f & 31) == 0) red[f >> 5] = s;
    __syncthreads();
    float inv = 1.0f / (sqrtf(red[0] + red[1]) + EPSF);
    p0 *= inv; p1 *= inv;

    float a  = angles[f];
    float ca = cosf(a), sa = sinf(a);
    float r0 = p0 * ca - p1 * sa;
    float r1 = p0 * sa + p1 * ca;

    g_Wh[b * STRIDE + 2 * f]     = __float2half_rn(r0);
    g_Wh[b * STRIDE + 2 * f + 1] = __float2half_rn(r1);
    g_Wh[b * STRIDE + D + f]     = __float2half_rn(kmw[b * NF + f]);
    if (f < 8) g_Wh[b * STRIDE + 192 + f] = __float2half_rn(0.f);

    g_rph[f * NB + b] = __floats2half2_rn(r0, r1);
    float x  = qraw[b * NF + f];
    float sp = fmaxf(x, 0.0f) + log1pf(expf(-fabsf(x)));
    g_ewmw[f * NB + b] = __floats2half2_rn(-sp, qmw[b * NF + f]);
}

// ---------------------------------------------------------------------------
// Fused kernel: blocks [0, KBLOCKS) do the K-path GEMM; the rest do Q-path.
// K path: 512 threads, 16 INDEPENDENT warps; each warp owns a 16x128 output
// strip. A fragments built in registers from global LDG (no STS/LDSM/barrier).
// W resident in smem (read-only after one initial sync).
// ---------------------------------------------------------------------------
constexpr int KTHREADS = 512;
constexpr int WARPS    = 16;
constexpr int TILES    = 2;                               // strips per warp
constexpr int KBLOCKS  = NK / (16 * WARPS * TILES);       // 1024

constexpr int QPB      = 64;
constexpr int QBLOCKS  = NQ / QPB;                        // 128

// kpath smem: W + bias.  qpath smem: 107,264 B (layout below).
constexpr int OFF_WH   = 0;
constexpr int OFF_BIAS = WBUF_BYTES;             // 51,200
constexpr int SMEM_SZ  = 107520;                 // max(kpath 51,712, qpath 107,264)

// ---- K path body -----------------------------------------------------------
__device__ __forceinline__ void kpath_body(char* smc, const float* __restrict__ Kmat,
                                           const float* __restrict__ kbias,
                                           float* __restrict__ out)
{
    const uint32_t base = smem_u32(smc);
    float* sBias = reinterpret_cast<float*>(smc + OFF_BIAS);

    const int tid  = threadIdx.x;
    const int lane = tid & 31;
    const int wid  = tid >> 5;          // 0..15

    // W -> smem (layout already final)
    {
        const int4* gw = reinterpret_cast<const int4*>(g_Wh);
        int4* sw = reinterpret_cast<int4*>(smc + OFF_WH);
        for (int i = tid; i < WBUF_BYTES / 16; i += KTHREADS) sw[i] = gw[i];
    }
    if (tid < NB) sBias[tid] = kbias[tid];

    // B (W) ldmatrix base address: bins (lane&7)+((lane>>4)&1)*8, k ((lane>>3)&1)*8
    const uint32_t bA = base + OFF_WH
        + (uint32_t)(((lane & 7) + ((lane >> 4) & 1) * 8) * STRIDE + ((lane >> 3) & 1) * 8) * 2;
    constexpr uint32_t MSTEP = 16 * STRIDE * 2;   // 16 bins in bytes

    const int r     = lane >> 2;        // 0..7   fragment row within strip
    const int cq    = lane & 3;         // 0..3   fragment col quad

    __syncthreads();   // W + bias visible; NO MORE BARRIERS.

    const float2* K2 = reinterpret_cast<const float2*>(Kmat);   // row stride 64
    const float4* K4 = reinterpret_cast<const float4*>(Kmat);   // row stride 32

    for (int t = 0; t < TILES; t++) {
        const int strip   = blockIdx.x * (WARPS * TILES) + t * WARPS + wid;
        const size_t rowBase = (size_t)strip * 16;
        const size_t ra = (rowBase + r) * 64;        // float2 index of row r
        const size_t rb = (rowBase + r + 8) * 64;    // float2 index of row r+8

        // accumulators: c[j][0..3] for n8 group j (cols j*8 + cq*2)
        float c[16][4];
        #pragma unroll
        for (int j = 0; j < 16; j++)
            #pragma unroll
            for (int q = 0; q < 4; q++) c[j][q] = 0.0f;

        // prefetch A chunk 0 (f32 pairs)
        float2 n0 = K2[ra + cq];
        float2 n1 = K2[rb + cq];
        float2 n2 = K2[ra + cq + 4];
        float2 n3 = K2[rb + cq + 4];

        #pragma unroll
        for (int kc = 0; kc < 12; kc++) {
            uint32_t af[4];
            if (kc < 8) {
                // A fragment from prefetched f32 pairs
                af[0] = packh2(n0.x, n0.y);
                af[1] = packh2(n1.x, n1.y);
                af[2] = packh2(n2.x, n2.y);
                af[3] = packh2(n3.x, n3.y);
                if (kc < 7) {       // prefetch next K chunk
                    const int o = (kc + 1) * 8 + cq;
                    n0 = K2[ra + o];
                    n1 = K2[rb + o];
                    n2 = K2[ra + o + 4];
                    n3 = K2[rb + o + 4];
                }
            } else {
                // magnitude chunk: mag cols (kc-8)*16 + cq*2 (+1), +8 (+9)
                // sources re-read rows already streamed -> L1 hits
                const int m0 = (kc - 8) * 16 + cq * 2;        // even
                const size_t ia = (rowBase + r) * 32 + (m0 >> 1);
                const size_t ib = (rowBase + r + 8) * 32 + (m0 >> 1);
                float4 q0 = K4[ia];
                float4 q1 = K4[ib];
                float4 q2 = K4[ia + 4];
                float4 q3 = K4[ib + 4];
                af[0] = packh2(sqrt_approx(fmaf(q0.x, q0.x, fmaf(q0.y, q0.y, EPSF))),
                               sqrt_approx(fmaf(q0.z, q0.z, fmaf(q0.w, q0.w, EPSF))));
                af[1] = packh2(sqrt_approx(fmaf(q1.x, q1.x, fmaf(q1.y, q1.y, EPSF))),
                               sqrt_approx(fmaf(q1.z, q1.z, fmaf(q1.w, q1.w, EPSF))));
                af[2] = packh2(sqrt_approx(fmaf(q2.x, q2.x, fmaf(q2.y, q2.y, EPSF))),
                               sqrt_approx(fmaf(q2.z, q2.z, fmaf(q2.w, q2.w, EPSF))));
                af[3] = packh2(sqrt_approx(fmaf(q3.x, q3.x, fmaf(q3.y, q3.y, EPSF))),
                               sqrt_approx(fmaf(q3.z, q3.z, fmaf(q3.w, q3.w, EPSF))));
            }

            const uint32_t kB = (uint32_t)kc * 32;
            #pragma unroll
            for (int jj = 0; jj < 8; jj++) {
                uint32_t bf[4];
                ldm4(bf, bA + jj * MSTEP + kB);
                mma16816(c[jj * 2],     af, &bf[0]);
                mma16816(c[jj * 2 + 1], af, &bf[2]);
            }
        }

        // epilogue: bias + STG.64 (no sync needed; warp-private rows)
        float2* out2 = reinterpret_cast<float2*>(out);
        const size_t o0 = (rowBase + r) * 64;
        const size_t o1 = (rowBase + r + 8) * 64;
        #pragma unroll
        for (int j = 0; j < 16; j++) {
            const int col = j * 8 + cq * 2;
            const float bx = sBias[col], by = sBias[col + 1];
            const int ch = col >> 1;
            out2[o0 + ch] = make_float2(c[j][0] + bx, c[j][1] + by);
            out2[o1 + ch] = make_float2(c[j][2] + bx, c[j][3] + by);
        }
    }
}

// ---- Q path body (64 queries per block, 512 threads) -----------------------
// smem: [0,32768) sRPh | [32768,65536) sEWMW | [65536,98304) sQn f32[64*128]
//       [98304,106496) sQmag half[64*64] | [106496,106752) sInv | [106752,107264) sQB
__device__ __forceinline__ void qpath_body(char* smc, const float* __restrict__ Q,
                                           const float* __restrict__ qbias,
                                           float* __restrict__ outq, int qb)
{
    __half2* sRPh  = reinterpret_cast<__half2*>(smc);            // [f][b]
    __half2* sEWMW = reinterpret_cast<__half2*>(smc + 32768);    // [f][b]
    float*   sQn   = reinterpret_cast<float*>(smc + 65536);      // QPB*D
    __half*  sQmag = reinterpret_cast<__half*>(smc + 98304);     // QPB*NF
    float*   sInv  = reinterpret_cast<float*>(smc + 106496);     // QPB
    float*   sQB   = reinterpret_cast<float*>(smc + 106752);     // NB

    const int tid = threadIdx.x;
    {
        const int4* gr = reinterpret_cast<const int4*>(g_rph);
        const int4* ge = reinterpret_cast<const int4*>(g_ewmw);
        int4* sr = reinterpret_cast<int4*>(sRPh);
        int4* se = reinterpret_cast<int4*>(sEWMW);
        #pragma unroll
        for (int it = 0; it < 4; it++) {
            sr[it * KTHREADS + tid] = gr[it * KTHREADS + tid];
            se[it * KTHREADS + tid] = ge[it * KTHREADS + tid];
        }
    }
    if (tid < NB) sQB[tid] = qbias[tid];

    const int qbase = qb * QPB;
    for (int i = tid; i < QPB * D; i += KTHREADS)
        sQn[i] = Q[(size_t)qbase * D + i];
    __syncthreads();

    {   // L2 norms: 8 threads per query (512 = 64*8)
        int q = tid >> 3, l8 = tid & 7;
        float s = 0.0f;
        #pragma unroll
        for (int j = 0; j < D / 8; j++) {
            float v = sQn[q * D + l8 + 8 * j];
            s = fmaf(v, v, s);
        }
        s += __shfl_down_sync(0xffffffffu, s, 4, 8);
        s += __shfl_down_sync(0xffffffffu, s, 2, 8);
        s += __shfl_down_sync(0xffffffffu, s, 1, 8);
        if (l8 == 0) sInv[q] = 1.0f / (sqrtf(s) + EPSF);
    }
    __syncthreads();
    for (int i = tid; i < QPB * D; i += KTHREADS)
        sQn[i] *= sInv[i >> 7];
    __syncthreads();
    for (int i = tid; i < QPB * NF; i += KTHREADS) {
        int q = i >> 6, f = i & 63;
        float a = sQn[q * D + 2 * f];
        float c = sQn[q * D + 2 * f + 1];
        sQmag[i] = __float2half_rn(sqrt_approx(fmaf(a, a, fmaf(c, c, EPSF))));
    }
    __syncthreads();

    const int b  = tid & 127;
    const int qg = tid >> 7;    // 0..3: 16 queries each
    float acc[16];
    #pragma unroll
    for (int j = 0; j < 16; j++) acc[j] = 0.0f;

    for (int f = 0; f < NF; f++) {
        float2 rp = __half22float2(sRPh[f * NB + b]);
        float2 em = __half22float2(sEWMW[f * NB + b]);   // x=eff_w, y=q_mag_w
        #pragma unroll
        for (int j = 0; j < 16; j++) {
            int q = qg * 16 + j;
            float2 qp = *reinterpret_cast<const float2*>(sQn + q * D + 2 * f);
            float d0 = rp.x - qp.x;
            float d1 = rp.y - qp.y;
            float dist = sqrt_approx(fmaf(d0, d0, fmaf(d1, d1, EPSF)));
            acc[j] = fmaf(dist, em.x, acc[j]);
            acc[j] = fmaf(__half2float(sQmag[q * NF + f]), em.y, acc[j]);
        }
    }

    #pragma unroll
    for (int j = 0; j < 16; j++) {
        int q = qbase + qg * 16 + j;
        outq[(size_t)q * NB + b] = acc[j] + sQB[b];
    }
}

// ---- Fused kernel -----------------------------------------------------------
__global__ void __launch_bounds__(KTHREADS, 1)
fused_kernel(const float* __restrict__ Kmat,
             const float* __restrict__ kbias,
             const float* __restrict__ Q,
             const float* __restrict__ qbias,
             float* __restrict__ out)
{
    extern __shared__ char smc[];
    if (blockIdx.x < KBLOCKS) {
        kpath_body(smc, Kmat, kbias, out);
    } else {
        qpath_body(smc, Q, qbias, out + (size_t)NK * NB, blockIdx.x - KBLOCKS);
    }
}

// ---------------------------------------------------------------------------
// Launch
// ---------------------------------------------------------------------------
extern "C" void kernel_launch(void* const* d_in, const int* in_sizes, int n_in,
                              void* d_out, int out_size)
{
    const float* Q      = (const float*)d_in[0];
    const float* Kmat   = (const float*)d_in[1];
    const float* angles = (const float*)d_in[2];
    const float* probes = (const float*)d_in[3];
    const float* kmw    = (const float*)d_in[4];
    const float* kbias  = (const float*)d_in[5];
    const float* qraw   = (const float*)d_in[6];
    const float* qmw    = (const float*)d_in[7];
    const float* qbias  = (const float*)d_in[8];
    float* out = (float*)d_out;

    cudaFuncSetAttribute(fused_kernel, cudaFuncAttributeMaxDynamicSharedMemorySize, SMEM_SZ);

    prep_kernel<<<NB, NF>>>(angles, probes, kmw, qraw, qmw);
    fused_kernel<<<KBLOCKS + QBLOCKS, KTHREADS, SMEM_SZ>>>(Kmat, kbias, Q, qbias, out);
}

// round 15
// speedup vs baseline: 1.3702x; 1.1460x over previous
#include <cuda_runtime.h>
#include <cuda_fp16.h>
#include <cstdint>

// ---------------------------------------------------------------------------
// Problem constants
// ---------------------------------------------------------------------------
#define EPSF 1e-8f

constexpr int NQ = 8192;     // queries
constexpr int NK = 524288;   // keys
constexpr int D  = 128;      // head_dim
constexpr int NF = 64;       // num_freqs
constexpr int NB = 128;      // num_bins
constexpr int DT = 192;      // D + NF  (GEMM K-dimension)

constexpr int STRIDE = 200;                    // fp16 elems per row (400B -> conflict-free ldmatrix)
constexpr int WBUF_BYTES = 128 * STRIDE * 2;   // 51,200 B

// ---------------------------------------------------------------------------
// Device scratch (no allocations allowed)
// ---------------------------------------------------------------------------
__device__ __align__(16) __half  g_Wh[128 * STRIDE];  // W fp16, [bin][k], stride 200
__device__ __align__(16) __half2 g_rph[NF * NB];      // rotated probe pairs fp16, [f][b]
__device__ __align__(16) __half2 g_ewmw[NF * NB];     // (eff_w, q_mag_w) fp16, [f][b]

// ---------------------------------------------------------------------------
// Helpers
// ---------------------------------------------------------------------------
__device__ __forceinline__ float sqrt_approx(float x) {
    float y;
    asm("sqrt.approx.f32 %0, %1;" : "=f"(y) : "f"(x));
    return y;
}

__device__ __forceinline__ uint32_t packh2(float a, float b) {
    __half2 t = __floats2half2_rn(a, b);
    return *reinterpret_cast<uint32_t*>(&t);
}

__device__ __forceinline__ uint32_t smem_u32(const void* p) {
    uint32_t a;
    asm("{ .reg .u64 t; cvta.to.shared.u64 t, %1; cvt.u32.u64 %0, t; }" : "=r"(a) : "l"(p));
    return a;
}

__device__ __forceinline__ void ldm4(uint32_t* r, uint32_t addr) {
    asm volatile("ldmatrix.sync.aligned.m8n8.x4.shared.b16 {%0,%1,%2,%3}, [%4];"
        : "=r"(r[0]), "=r"(r[1]), "=r"(r[2]), "=r"(r[3]) : "r"(addr));
}

__device__ __forceinline__ void mma16816(float* c, const uint32_t* a, const uint32_t* b) {
    asm volatile("mma.sync.aligned.m16n8k16.row.col.f32.f16.f16.f32 "
        "{%0,%1,%2,%3}, {%4,%5,%6,%7}, {%8,%9}, {%0,%1,%2,%3};"
        : "+f"(c[0]), "+f"(c[1]), "+f"(c[2]), "+f"(c[3])
        : "r"(a[0]), "r"(a[1]), "r"(a[2]), "r"(a[3]), "r"(b[0]), "r"(b[1]));
}

// ---------------------------------------------------------------------------
// Prep kernel: one block per bin, 64 threads (one per freq)
// ---------------------------------------------------------------------------
__global__ void prep_kernel(const float* __restrict__ angles,
                            const float* __restrict__ probes,
                            const float* __restrict__ kmw,
                            const float* __restrict__ qraw,
                            const float* __restrict__ qmw)
{
    __shared__ float red[2];
    const int b = blockIdx.x;
    const int f = threadIdx.x;   // 0..63

    float p0 = probes[b * D + 2 * f];
    float p1 = probes[b * D + 2 * f + 1];
    float s = fmaf(p0, p0, p1 * p1);
    #pragma unroll
    for (int o = 16; o; o >>= 1) s += __shfl_xor_sync(0xffffffffu, s, o);
    if ((f & 31) == 0) red[f >> 5] = s;
    __syncthreads();
    float inv = 1.0f / (sqrtf(red[0] + red[1]) + EPSF);
    p0 *= inv; p1 *= inv;

    float a  = angles[f];
    float ca = cosf(a), sa = sinf(a);
    float r0 = p0 * ca - p1 * sa;
    float r1 = p0 * sa + p1 * ca;

    g_Wh[b * STRIDE + 2 * f]     = __float2half_rn(r0);
    g_Wh[b * STRIDE + 2 * f + 1] = __float2half_rn(r1);
    g_Wh[b * STRIDE + D + f]     = __float2half_rn(kmw[b * NF + f]);
    if (f < 8) g_Wh[b * STRIDE + 192 + f] = __float2half_rn(0.f);

    g_rph[f * NB + b] = __floats2half2_rn(r0, r1);
    float x  = qraw[b * NF + f];
    float sp = fmaxf(x, 0.0f) + log1pf(expf(-fabsf(x)));
    g_ewmw[f * NB + b] = __floats2half2_rn(-sp, qmw[b * NF + f]);
}

// ---------------------------------------------------------------------------
// Fused kernel. Grid layout: blocks [0, QBLOCKS) run the Q-path (front-loaded
// so they pack under the K-path waves); blocks [QBLOCKS, QBLOCKS+KBLOCKS)
// run the K-path GEMM.
// K path: 512 threads, 16 warps as 4(M)x4(N) grid of 32x32 warp tiles,
// block tile 128x128, double-buffered A, register prefetch of next tile's
// raw K converted inside the MMA loop (the R9 mainloop, best measured).
// TILES=2 halves the tail quantum vs TILES=4.
// ---------------------------------------------------------------------------
constexpr int TILE_M   = 128;
constexpr int KTHREADS = 512;
constexpr int TILES    = 2;
constexpr int KBLOCKS  = NK / (TILE_M * TILES);           // 2048
constexpr int FPT      = (TILE_M * (D / 4)) / KTHREADS;   // float4 per thread = 8

constexpr int QPB      = 64;
constexpr int QBLOCKS  = NQ / QPB;                        // 128

// kpath smem layout
constexpr int OFF_WH   = 0;
constexpr int OFF_A0   = OFF_WH + WBUF_BYTES;    //  51,200
constexpr int OFF_A1   = OFF_A0 + WBUF_BYTES;    // 102,400
constexpr int OFF_BIAS = OFF_A1 + WBUF_BYTES;    // 153,600
constexpr int SMEM_SZ  = OFF_BIAS + 512;         // 154,112

// qpath smem layout (fp16 tables, fits in SMEM_SZ):
// [0,32768) sRPh | [32768,65536) sEWMW | [65536,98304) sQn f32[64*128]
// [98304,106496) sQmag half[64*64] | [106496,106752) sInv | [106752,107264) sQB

// ---- K path body -----------------------------------------------------------
__device__ __forceinline__ void kpath_body(char* smc, int kbid,
                                           const float* __restrict__ Kmat,
                                           const float* __restrict__ kbias,
                                           float* __restrict__ out)
{
    const uint32_t base = smem_u32(smc);
    float* sBias = reinterpret_cast<float*>(smc + OFF_BIAS);

    const int tid  = threadIdx.x;
    const int lane = tid & 31;
    const int wid  = tid >> 5;
    const int wm   = (wid & 3) * 32;    // warp M offset
    const int wn   = (wid >> 2) * 32;   // warp N offset

    // W -> smem (layout already final)
    {
        const int4* gw = reinterpret_cast<const int4*>(g_Wh);
        int4* sw = reinterpret_cast<int4*>(smc + OFF_WH);
        for (int i = tid; i < WBUF_BYTES / 16; i += KTHREADS) sw[i] = gw[i];
    }
    if (tid < NB) sBias[tid] = kbias[tid];

    // ldmatrix lane base addresses
    const int aRow = wm + (lane & 7) + ((lane >> 3) & 1) * 8;
    const int aK   = ((lane >> 4) & 1) * 8;
    const uint32_t aFragOff = (uint32_t)(aRow * STRIDE + aK) * 2;
    const uint32_t aA[2] = { base + OFF_A0 + aFragOff, base + OFF_A1 + aFragOff };
    const int bRow = wn + (lane & 7) + ((lane >> 4) & 1) * 8;
    const int bK   = ((lane >> 3) & 1) * 8;
    const uint32_t bA = base + OFF_WH + (uint32_t)(bRow * STRIDE + bK) * 2;

    constexpr uint32_t MSTEP = 16 * STRIDE * 2;   // 16 rows in bytes

    const size_t blockRow0 = (size_t)kbid * TILES * TILE_M;
    const float4* K4base = reinterpret_cast<const float4*>(Kmat);

    // ---- Prologue: LDG tile0 -> regs, convert -> A0, LDG tile1 -> regs
    float4 pf[FPT];
    {
        const float4* g = K4base + blockRow0 * (D / 4);
        #pragma unroll
        for (int it = 0; it < FPT; it++) pf[it] = g[it * KTHREADS + tid];
    }
    #pragma unroll
    for (int it = 0; it < FPT; it++) {
        const int i = it * KTHREADS + tid;
        const int row = i >> 5, c4 = i & 31;
        float4 v = pf[it];
        const int e0 = row * STRIDE + 4 * c4;
        *reinterpret_cast<uint2*>(smc + OFF_A0 + 2 * e0) =
            make_uint2(packh2(v.x, v.y), packh2(v.z, v.w));
        float m0 = sqrt_approx(fmaf(v.x, v.x, fmaf(v.y, v.y, EPSF)));
        float m1 = sqrt_approx(fmaf(v.z, v.z, fmaf(v.w, v.w, EPSF)));
        const int em = row * STRIDE + D + 2 * c4;
        *reinterpret_cast<uint32_t*>(smc + OFF_A0 + 2 * em) = packh2(m0, m1);
    }
    {
        const float4* g = K4base + (blockRow0 + TILE_M) * (D / 4);
        #pragma unroll
        for (int it = 0; it < FPT; it++) pf[it] = g[it * KTHREADS + tid];
    }
    __syncthreads();   // W + bias + A0 visible to all

    #pragma unroll
    for (int t = 0; t < TILES; t++) {
        const size_t rowBase = blockRow0 + (size_t)t * TILE_M;
        const bool doConv = (t + 1 < TILES);
        const uint32_t aCur = aA[t & 1];
        char* nxtBase = smc + OFF_A0 + ((t + 1) & 1) * WBUF_BYTES;

        // ---- MMA mainloop with interleaved convert (kc < FPT)
        float c[2][4][4];
        #pragma unroll
        for (int i = 0; i < 2; i++)
            #pragma unroll
            for (int j = 0; j < 4; j++)
                #pragma unroll
                for (int r = 0; r < 4; r++) c[i][j][r] = 0.0f;

        #pragma unroll
        for (int kc = 0; kc < DT / 16; kc++) {
            const uint32_t kB = (uint32_t)kc * 32;
            uint32_t af[2][4], bf[2][4];
            #pragma unroll
            for (int i = 0; i < 2; i++) ldm4(af[i], aCur + i * MSTEP + kB);
            #pragma unroll
            for (int jj = 0; jj < 2; jj++) ldm4(bf[jj], bA + jj * MSTEP + kB);
            #pragma unroll
            for (int i = 0; i < 2; i++)
                #pragma unroll
                for (int j = 0; j < 4; j++)
                    mma16816(c[i][j], af[i], &bf[j >> 1][(j & 1) * 2]);

            if (kc < FPT && doConv) {    // convert one pf chunk -> A_next
                const int i = kc * KTHREADS + (int)threadIdx.x;
                const int row = i >> 5, c4 = i & 31;
                float4 v = pf[kc];
                const int e0 = row * STRIDE + 4 * c4;
                *reinterpret_cast<uint2*>(nxtBase + 2 * e0) =
                    make_uint2(packh2(v.x, v.y), packh2(v.z, v.w));
                float m0 = sqrt_approx(fmaf(v.x, v.x, fmaf(v.y, v.y, EPSF)));
                float m1 = sqrt_approx(fmaf(v.z, v.z, fmaf(v.w, v.w, EPSF)));
                const int em = row * STRIDE + D + 2 * c4;
                *reinterpret_cast<uint32_t*>(nxtBase + 2 * em) = packh2(m0, m1);
            }
        }

        // ---- Epilogue: bias + STG.64 from accumulators
        float2* out2 = reinterpret_cast<float2*>(out);
        const size_t r0 = rowBase + wm + (lane >> 2);
        #pragma unroll
        for (int j = 0; j < 4; j++) {
            const int col = wn + j * 8 + (lane & 3) * 2;
            const float bx = sBias[col], by = sBias[col + 1];
            const int ch = col >> 1;
            #pragma unroll
            for (int i = 0; i < 2; i++) {
                const size_t row = r0 + i * 16;
                float2 v0 = make_float2(c[i][j][0] + bx, c[i][j][1] + by);
                float2 v1 = make_float2(c[i][j][2] + bx, c[i][j][3] + by);
                out2[row * (NB / 2) + ch] = v0;
                out2[(row + 8) * (NB / 2) + ch] = v1;
            }
        }
        if (doConv) __syncthreads();   // A_next fully converted; A_cur reads done
    }
}

// ---- Q path body (64 queries per block, 512 threads, fp16 tables) ----------
__device__ __forceinline__ void qpath_body(char* smc, const float* __restrict__ Q,
                                           const float* __restrict__ qbias,
                                           float* __restrict__ outq, int qb)
{
    __half2* sRPh  = reinterpret_cast<__half2*>(smc);            // [f][b]
    __half2* sEWMW = reinterpret_cast<__half2*>(smc + 32768);    // [f][b]
    float*   sQn   = reinterpret_cast<float*>(smc + 65536);      // QPB*D
    __half*  sQmag = reinterpret_cast<__half*>(smc + 98304);     // QPB*NF
    float*   sInv  = reinterpret_cast<float*>(smc + 106496);     // QPB
    float*   sQB   = reinterpret_cast<float*>(smc + 106752);     // NB

    const int tid = threadIdx.x;
    {
        const int4* gr = reinterpret_cast<const int4*>(g_rph);
        const int4* ge = reinterpret_cast<const int4*>(g_ewmw);
        int4* sr = reinterpret_cast<int4*>(sRPh);
        int4* se = reinterpret_cast<int4*>(sEWMW);
        #pragma unroll
        for (int it = 0; it < 4; it++) {
            sr[it * KTHREADS + tid] = gr[it * KTHREADS + tid];
            se[it * KTHREADS + tid] = ge[it * KTHREADS + tid];
        }
    }
    if (tid < NB) sQB[tid] = qbias[tid];

    const int qbase = qb * QPB;
    for (int i = tid; i < QPB * D; i += KTHREADS)
        sQn[i] = Q[(size_t)qbase * D + i];
    __syncthreads();

    {   // L2 norms: 8 threads per query (512 = 64*8)
        int q = tid >> 3, l8 = tid & 7;
        float s = 0.0f;
        #pragma unroll
        for (int j = 0; j < D / 8; j++) {
            float v = sQn[q * D + l8 + 8 * j];
            s = fmaf(v, v, s);
        }
        s += __shfl_down_sync(0xffffffffu, s, 4, 8);
        s += __shfl_down_sync(0xffffffffu, s, 2, 8);
        s += __shfl_down_sync(0xffffffffu, s, 1, 8);
        if (l8 == 0) sInv[q] = 1.0f / (sqrtf(s) + EPSF);
    }
    __syncthreads();
    for (int i = tid; i < QPB * D; i += KTHREADS)
        sQn[i] *= sInv[i >> 7];
    __syncthreads();
    for (int i = tid; i < QPB * NF; i += KTHREADS) {
        int q = i >> 6, f = i & 63;
        float a = sQn[q * D + 2 * f];
        float c = sQn[q * D + 2 * f + 1];
        sQmag[i] = __float2half_rn(sqrt_approx(fmaf(a, a, fmaf(c, c, EPSF))));
    }
    __syncthreads();

    const int b  = tid & 127;
    const int qg = tid >> 7;    // 0..3: 16 queries each
    float acc[16];
    #pragma unroll
    for (int j = 0; j < 16; j++) acc[j] = 0.0f;

    for (int f = 0; f < NF; f++) {
        float2 rp = __half22float2(sRPh[f * NB + b]);
        float2 em = __half22float2(sEWMW[f * NB + b]);   // x=eff_w, y=q_mag_w
        #pragma unroll
        for (int j = 0; j < 16; j++) {
            int q = qg * 16 + j;
            float2 qp = *reinterpret_cast<const float2*>(sQn + q * D + 2 * f);
            float d0 = rp.x - qp.x;
            float d1 = rp.y - qp.y;
            float dist = sqrt_approx(fmaf(d0, d0, fmaf(d1, d1, EPSF)));
            acc[j] = fmaf(dist, em.x, acc[j]);
            acc[j] = fmaf(__half2float(sQmag[q * NF + f]), em.y, acc[j]);
        }
    }

    #pragma unroll
    for (int j = 0; j < 16; j++) {
        int q = qbase + qg * 16 + j;
        outq[(size_t)q * NB + b] = acc[j] + sQB[b];
    }
}

// ---- Fused kernel (qpath blocks FIRST so they pack under kpath waves) ------
__global__ void __launch_bounds__(KTHREADS, 1)
fused_kernel(const float* __restrict__ Kmat,
             const float* __restrict__ kbias,
             const float* __restrict__ Q,
             const float* __restrict__ qbias,
             float* __restrict__ out)
{
    extern __shared__ char smc[];
    if (blockIdx.x < QBLOCKS) {
        qpath_body(smc, Q, qbias, out + (size_t)NK * NB, blockIdx.x);
    } else {
        kpath_body(smc, blockIdx.x - QBLOCKS, Kmat, kbias, out);
    }
}

// ---------------------------------------------------------------------------
// Launch
// ---------------------------------------------------------------------------
extern "C" void kernel_launch(void* const* d_in, const int* in_sizes, int n_in,
                              void* d_out, int out_size)
{
    const float* Q      = (const float*)d_in[0];
    const float* Kmat   = (const float*)d_in[1];
    const float* angles = (const float*)d_in[2];
    const float* probes = (const float*)d_in[3];
    const float* kmw    = (const float*)d_in[4];
    const float* kbias  = (const float*)d_in[5];
    const float* qraw   = (const float*)d_in[6];
    const float* qmw    = (const float*)d_in[7];
    const float* qbias  = (const float*)d_in[8];
    float* out = (float*)d_out;

    cudaFuncSetAttribute(fused_kernel, cudaFuncAttributeMaxDynamicSharedMemorySize, SMEM_SZ);

    prep_kernel<<<NB, NF>>>(angles, probes, kmw, qraw, qmw);
    fused_kernel<<<QBLOCKS + KBLOCKS, KTHREADS, SMEM_SZ>>>(Kmat, kbias, Q, qbias, out);
}

// round 16
// speedup vs baseline: 1.4530x; 1.0604x over previous
#include <cuda_runtime.h>
#include <cuda_fp16.h>
#include <cstdint>

// ---------------------------------------------------------------------------
// Problem constants
// ---------------------------------------------------------------------------
#define EPSF 1e-8f

constexpr int NQ = 8192;     // queries
constexpr int NK = 524288;   // keys
constexpr int D  = 128;      // head_dim
constexpr int NF = 64;       // num_freqs
constexpr int NB = 128;      // num_bins
constexpr int DT = 192;      // D + NF  (GEMM K-dimension)

constexpr int STRIDE = 200;                    // fp16 elems per row (400B -> conflict-free ldmatrix)
constexpr int WBUF_BYTES = 128 * STRIDE * 2;   // 51,200 B

// ---------------------------------------------------------------------------
// Device scratch (no allocations allowed)
// ---------------------------------------------------------------------------
__device__ __align__(16) __half  g_Wh[128 * STRIDE];  // W fp16, [bin][k], stride 200
__device__ __align__(16) __half2 g_rph[NF * NB];      // rotated probe pairs fp16, [f][b]
__device__ __align__(16) __half2 g_ewmw[NF * NB];     // (eff_w, q_mag_w) fp16, [f][b]

// ---------------------------------------------------------------------------
// Helpers
// ---------------------------------------------------------------------------
__device__ __forceinline__ float sqrt_approx(float x) {
    float y;
    asm("sqrt.approx.f32 %0, %1;" : "=f"(y) : "f"(x));
    return y;
}

__device__ __forceinline__ uint32_t packh2(float a, float b) {
    __half2 t = __floats2half2_rn(a, b);
    return *reinterpret_cast<uint32_t*>(&t);
}

__device__ __forceinline__ uint32_t smem_u32(const void* p) {
    uint32_t a;
    asm("{ .reg .u64 t; cvta.to.shared.u64 t, %1; cvt.u32.u64 %0, t; }" : "=r"(a) : "l"(p));
    return a;
}

__device__ __forceinline__ void ldm4(uint32_t* r, uint32_t addr) {
    asm volatile("ldmatrix.sync.aligned.m8n8.x4.shared.b16 {%0,%1,%2,%3}, [%4];"
        : "=r"(r[0]), "=r"(r[1]), "=r"(r[2]), "=r"(r[3]) : "r"(addr));
}

__device__ __forceinline__ void mma16816(float* c, const uint32_t* a, const uint32_t* b) {
    asm volatile("mma.sync.aligned.m16n8k16.row.col.f32.f16.f16.f32 "
        "{%0,%1,%2,%3}, {%4,%5,%6,%7}, {%8,%9}, {%0,%1,%2,%3};"
        : "+f"(c[0]), "+f"(c[1]), "+f"(c[2]), "+f"(c[3])
        : "r"(a[0]), "r"(a[1]), "r"(a[2]), "r"(a[3]), "r"(b[0]), "r"(b[1]));
}

// named barriers: producer/consumer handoff (512 = full block)
#define BAR_ARRIVE(id) asm volatile("bar.arrive %0, %1;" :: "r"(id), "r"(512) : "memory")
#define BAR_SYNC(id)   asm volatile("bar.sync %0, %1;"   :: "r"(id), "r"(512) : "memory")

// ---------------------------------------------------------------------------
// Prep kernel: one block per bin, 64 threads (one per freq)
// ---------------------------------------------------------------------------
__global__ void prep_kernel(const float* __restrict__ angles,
                            const float* __restrict__ probes,
                            const float* __restrict__ kmw,
                            const float* __restrict__ qraw,
                            const float* __restrict__ qmw)
{
    __shared__ float red[2];
    const int b = blockIdx.x;
    const int f = threadIdx.x;   // 0..63

    float p0 = probes[b * D + 2 * f];
    float p1 = probes[b * D + 2 * f + 1];
    float s = fmaf(p0, p0, p1 * p1);
    #pragma unroll
    for (int o = 16; o; o >>= 1) s += __shfl_xor_sync(0xffffffffu, s, o);
    if ((f & 31) == 0) red[f >> 5] = s;
    __syncthreads();
    float inv = 1.0f / (sqrtf(red[0] + red[1]) + EPSF);
    p0 *= inv; p1 *= inv;

    float a  = angles[f];
    float ca = cosf(a), sa = sinf(a);
    float r0 = p0 * ca - p1 * sa;
    float r1 = p0 * sa + p1 * ca;

    g_Wh[b * STRIDE + 2 * f]     = __float2half_rn(r0);
    g_Wh[b * STRIDE + 2 * f + 1] = __float2half_rn(r1);
    g_Wh[b * STRIDE + D + f]     = __float2half_rn(kmw[b * NF + f]);
    if (f < 8) g_Wh[b * STRIDE + 192 + f] = __float2half_rn(0.f);

    g_rph[f * NB + b] = __floats2half2_rn(r0, r1);
    float x  = qraw[b * NF + f];
    float sp = fmaxf(x, 0.0f) + log1pf(expf(-fabsf(x)));
    g_ewmw[f * NB + b] = __floats2half2_rn(-sp, qmw[b * NF + f]);
}

// ---------------------------------------------------------------------------
// Fused kernel. Blocks [0, QBLOCKS) = Q-path (front-loaded); rest = K-path.
// K path: warp-specialized. 512 threads: warps 0-7 consumers (pure
// LDSM+HMMA+epilogue, 64x32 warp tiles in 2Mx4N grid, block tile 128x128);
// warps 8-15 producers (LDG f32 -> convert -> STS into double-buffered A).
// Named barriers full/empty per buffer decouple the two streams.
// ---------------------------------------------------------------------------
constexpr int TILE_M   = 128;
constexpr int KTHREADS = 512;
constexpr int TILES    = 4;
constexpr int KBLOCKS  = NK / (TILE_M * TILES);           // 1024

constexpr int QPB      = 64;
constexpr int QBLOCKS  = NQ / QPB;                        // 128

// kpath smem layout
constexpr int OFF_WH   = 0;
constexpr int OFF_A0   = OFF_WH + WBUF_BYTES;    //  51,200
constexpr int OFF_A1   = OFF_A0 + WBUF_BYTES;    // 102,400
constexpr int OFF_BIAS = OFF_A1 + WBUF_BYTES;    // 153,600
constexpr int SMEM_SZ  = OFF_BIAS + 512;         // 154,112

// qpath smem layout (fp16 tables, fits in SMEM_SZ):
// [0,32768) sRPh | [32768,65536) sEWMW | [65536,98304) sQn f32[64*128]
// [98304,106496) sQmag half[64*64] | [106496,106752) sInv | [106752,107264) sQB

// ---- K path body -----------------------------------------------------------
__device__ __forceinline__ void kpath_body(char* smc, int kbid,
                                           const float* __restrict__ Kmat,
                                           const float* __restrict__ kbias,
                                           float* __restrict__ out)
{
    const uint32_t base = smem_u32(smc);
    float* sBias = reinterpret_cast<float*>(smc + OFF_BIAS);

    const int tid  = threadIdx.x;
    const int lane = tid & 31;
    const int wid  = tid >> 5;          // 0..15

    // W + bias -> smem (all 512 threads)
    {
        const int4* gw = reinterpret_cast<const int4*>(g_Wh);
        int4* sw = reinterpret_cast<int4*>(smc + OFF_WH);
        for (int i = tid; i < WBUF_BYTES / 16; i += KTHREADS) sw[i] = gw[i];
    }
    if (tid < NB) sBias[tid] = kbias[tid];
    __syncthreads();   // W + bias visible (barrier 0; only block-wide sync)

    const size_t blockRow0 = (size_t)kbid * TILES * TILE_M;
    const float4* K4base = reinterpret_cast<const float4*>(Kmat);

    if (wid >= 8) {
        // ================= PRODUCER warps (8..15; 256 threads) ==============
        const int tp = tid - 256;   // 0..255
        for (int t = 0; t < TILES; t++) {
            const int b = t & 1;
            if (t >= 2) BAR_SYNC(3 + b);              // wait empty[b]
            char* dst = smc + OFF_A0 + b * WBUF_BYTES;
            const float4* g = K4base + (blockRow0 + (size_t)t * TILE_M) * (D / 4);
            #pragma unroll
            for (int ib = 0; ib < 4; ib++) {
                float4 vv[4];
                #pragma unroll
                for (int u = 0; u < 4; u++)
                    vv[u] = g[(ib * 4 + u) * 256 + tp];
                #pragma unroll
                for (int u = 0; u < 4; u++) {
                    const int i = (ib * 4 + u) * 256 + tp;
                    const int row = i >> 5, c4 = i & 31;
                    float4 v = vv[u];
                    const int e0 = row * STRIDE + 4 * c4;
                    *reinterpret_cast<uint2*>(dst + 2 * e0) =
                        make_uint2(packh2(v.x, v.y), packh2(v.z, v.w));
                    float m0 = sqrt_approx(fmaf(v.x, v.x, fmaf(v.y, v.y, EPSF)));
                    float m1 = sqrt_approx(fmaf(v.z, v.z, fmaf(v.w, v.w, EPSF)));
                    const int em = row * STRIDE + D + 2 * c4;
                    *reinterpret_cast<uint32_t*>(dst + 2 * em) = packh2(m0, m1);
                }
            }
            BAR_ARRIVE(1 + b);                        // signal full[b]
        }
    } else {
        // ================= CONSUMER warps (0..7; 256 threads) ===============
        const int wm = (wid & 1) * 64;     // warp M offset (2 groups of 64)
        const int wn = (wid >> 1) * 32;    // warp N offset (4 groups of 32)

        // ldmatrix lane base addresses
        const int aRow = wm + (lane & 7) + ((lane >> 3) & 1) * 8;
        const int aK   = ((lane >> 4) & 1) * 8;
        const uint32_t aFragOff = (uint32_t)(aRow * STRIDE + aK) * 2;
        const uint32_t aA[2] = { base + OFF_A0 + aFragOff, base + OFF_A1 + aFragOff };
        const int bRow = wn + (lane & 7) + ((lane >> 4) & 1) * 8;
        const int bK   = ((lane >> 3) & 1) * 8;
        const uint32_t bA = base + OFF_WH + (uint32_t)(bRow * STRIDE + bK) * 2;
        constexpr uint32_t MSTEP = 16 * STRIDE * 2;   // 16 rows in bytes

        for (int t = 0; t < TILES; t++) {
            const int b = t & 1;
            BAR_SYNC(1 + b);                          // wait full[b]
            const uint32_t aCur = aA[b];
            const size_t rowBase = blockRow0 + (size_t)t * TILE_M;

            float c[4][4][4];
            #pragma unroll
            for (int i = 0; i < 4; i++)
                #pragma unroll
                for (int j = 0; j < 4; j++)
                    #pragma unroll
                    for (int r = 0; r < 4; r++) c[i][j][r] = 0.0f;

            #pragma unroll
            for (int kc = 0; kc < DT / 16; kc++) {
                const uint32_t kB = (uint32_t)kc * 32;
                uint32_t af[4][4], bf[2][4];
                #pragma unroll
                for (int i = 0; i < 4; i++) ldm4(af[i], aCur + i * MSTEP + kB);
                #pragma unroll
                for (int jj = 0; jj < 2; jj++) ldm4(bf[jj], bA + jj * MSTEP + kB);
                #pragma unroll
                for (int i = 0; i < 4; i++)
                    #pragma unroll
                    for (int j = 0; j < 4; j++)
                        mma16816(c[i][j], af[i], &bf[j >> 1][(j & 1) * 2]);
            }

            BAR_ARRIVE(3 + b);                        // release empty[b] BEFORE epilogue

            // ---- Epilogue: bias + STG.64 from accumulators
            float2* out2 = reinterpret_cast<float2*>(out);
            const size_t r0 = rowBase + wm + (lane >> 2);
            #pragma unroll
            for (int j = 0; j < 4; j++) {
                const int col = wn + j * 8 + (lane & 3) * 2;
                const float bx = sBias[col], by = sBias[col + 1];
                const int ch = col >> 1;
                #pragma unroll
                for (int i = 0; i < 4; i++) {
                    const size_t row = r0 + i * 16;
                    float2 v0 = make_float2(c[i][j][0] + bx, c[i][j][1] + by);
                    float2 v1 = make_float2(c[i][j][2] + bx, c[i][j][3] + by);
                    out2[row * (NB / 2) + ch] = v0;
                    out2[(row + 8) * (NB / 2) + ch] = v1;
                }
            }
        }
    }
}

// ---- Q path body (64 queries per block, 512 threads, fp16 tables) ----------
__device__ __forceinline__ void qpath_body(char* smc, const float* __restrict__ Q,
                                           const float* __restrict__ qbias,
                                           float* __restrict__ outq, int qb)
{
    __half2* sRPh  = reinterpret_cast<__half2*>(smc);            // [f][b]
    __half2* sEWMW = reinterpret_cast<__half2*>(smc + 32768);    // [f][b]
    float*   sQn   = reinterpret_cast<float*>(smc + 65536);      // QPB*D
    __half*  sQmag = reinterpret_cast<__half*>(smc + 98304);     // QPB*NF
    float*   sInv  = reinterpret_cast<float*>(smc + 106496);     // QPB
    float*   sQB   = reinterpret_cast<float*>(smc + 106752);     // NB

    const int tid = threadIdx.x;
    {
        const int4* gr = reinterpret_cast<const int4*>(g_rph);
        const int4* ge = reinterpret_cast<const int4*>(g_ewmw);
        int4* sr = reinterpret_cast<int4*>(sRPh);
        int4* se = reinterpret_cast<int4*>(sEWMW);
        #pragma unroll
        for (int it = 0; it < 4; it++) {
            sr[it * KTHREADS + tid] = gr[it * KTHREADS + tid];
            se[it * KTHREADS + tid] = ge[it * KTHREADS + tid];
        }
    }
    if (tid < NB) sQB[tid] = qbias[tid];

    const int qbase = qb * QPB;
    for (int i = tid; i < QPB * D; i += KTHREADS)
        sQn[i] = Q[(size_t)qbase * D + i];
    __syncthreads();

    {   // L2 norms: 8 threads per query (512 = 64*8)
        int q = tid >> 3, l8 = tid & 7;
        float s = 0.0f;
        #pragma unroll
        for (int j = 0; j < D / 8; j++) {
            float v = sQn[q * D + l8 + 8 * j];
            s = fmaf(v, v, s);
        }
        s += __shfl_down_sync(0xffffffffu, s, 4, 8);
        s += __shfl_down_sync(0xffffffffu, s, 2, 8);
        s += __shfl_down_sync(0xffffffffu, s, 1, 8);
        if (l8 == 0) sInv[q] = 1.0f / (sqrtf(s) + EPSF);
    }
    __syncthreads();
    for (int i = tid; i < QPB * D; i += KTHREADS)
        sQn[i] *= sInv[i >> 7];
    __syncthreads();
    for (int i = tid; i < QPB * NF; i += KTHREADS) {
        int q = i >> 6, f = i & 63;
        float a = sQn[q * D + 2 * f];
        float c = sQn[q * D + 2 * f + 1];
        sQmag[i] = __float2half_rn(sqrt_approx(fmaf(a, a, fmaf(c, c, EPSF))));
    }
    __syncthreads();

    const int b  = tid & 127;
    const int qg = tid >> 7;    // 0..3: 16 queries each
    float acc[16];
    #pragma unroll
    for (int j = 0; j < 16; j++) acc[j] = 0.0f;

    for (int f = 0; f < NF; f++) {
        float2 rp = __half22float2(sRPh[f * NB + b]);
        float2 em = __half22float2(sEWMW[f * NB + b]);   // x=eff_w, y=q_mag_w
        #pragma unroll
        for (int j = 0; j < 16; j++) {
            int q = qg * 16 + j;
            float2 qp = *reinterpret_cast<const float2*>(sQn + q * D + 2 * f);
            float d0 = rp.x - qp.x;
            float d1 = rp.y - qp.y;
            float dist = sqrt_approx(fmaf(d0, d0, fmaf(d1, d1, EPSF)));
            acc[j] = fmaf(dist, em.x, acc[j]);
            acc[j] = fmaf(__half2float(sQmag[q * NF + f]), em.y, acc[j]);
        }
    }

    #pragma unroll
    for (int j = 0; j < 16; j++) {
        int q = qbase + qg * 16 + j;
        outq[(size_t)q * NB + b] = acc[j] + sQB[b];
    }
}

// ---- Fused kernel (qpath blocks FIRST so they pack under kpath waves) ------
__global__ void __launch_bounds__(KTHREADS, 1)
fused_kernel(const float* __restrict__ Kmat,
             const float* __restrict__ kbias,
             const float* __restrict__ Q,
             const float* __restrict__ qbias,
             float* __restrict__ out)
{
    extern __shared__ char smc[];
    if (blockIdx.x < QBLOCKS) {
        qpath_body(smc, Q, qbias, out + (size_t)NK * NB, blockIdx.x);
    } else {
        kpath_body(smc, blockIdx.x - QBLOCKS, Kmat, kbias, out);
    }
}

// ---------------------------------------------------------------------------
// Launch
// ---------------------------------------------------------------------------
extern "C" void kernel_launch(void* const* d_in, const int* in_sizes, int n_in,
                              void* d_out, int out_size)
{
    const float* Q      = (const float*)d_in[0];
    const float* Kmat   = (const float*)d_in[1];
    const float* angles = (const float*)d_in[2];
    const float* probes = (const float*)d_in[3];
    const float* kmw    = (const float*)d_in[4];
    const float* kbias  = (const float*)d_in[5];
    const float* qraw   = (const float*)d_in[6];
    const float* qmw    = (const float*)d_in[7];
    const float* qbias  = (const float*)d_in[8];
    float* out = (float*)d_out;

    cudaFuncSetAttribute(fused_kernel, cudaFuncAttributeMaxDynamicSharedMemorySize, SMEM_SZ);

    prep_kernel<<<NB, NF>>>(angles, probes, kmw, qraw, qmw);
    fused_kernel<<<QBLOCKS + KBLOCKS, KTHREADS, SMEM_SZ>>>(Kmat, kbias, Q, qbias, out);
}